// round 14
// baseline (speedup 1.0000x reference)
#include <cuda_runtime.h>
#include <cstddef>
#include <cstdint>

// CSPN_6468220748336 — R10 winner + batch-interleaved block scheduling:
// grid = (W/BX, B, H/BY) so a resident wave spans all 8 batches (full
// 421MB gw spread across DRAM banks/L2 sets) instead of ~2 batches.
// Kernel body identical to the 65.57us best.
// out[b,y,x] = sum_{i,j} gw[b, i*7+j, y+3, x+3] * src[b, y+3-i, x+3-j]
//   src = h0 at (i,j)=(3,3), else hn; zero-padded outside [0,512)^2.

namespace {
constexpr int K  = 7;
constexpr int K2 = 49;
constexpr int B  = 8;
constexpr int H  = 512;
constexpr int W  = 512;
constexpr int WP = 518;
constexpr int PLANE = WP * WP;

constexpr int BX = 128;                // output cols per block
constexpr int BY = 4;                  // output rows per block (1 warp/row)
constexpr int NT = 128;                // 4 warps

constexpr int Q  = 8;                  // prefetch lookahead (taps), ring size

constexpr int TILE_W = 140;            // hn halo cols [X0-3, X0+137)
constexpr int TILE_H = BY + K - 1;     // 10 halo rows [Y0-3, Y0+7)
}

template <int D>
__device__ __forceinline__ void row_compute(
    const float* __restrict__ p0,        // aligned float4 base, tap 0 (this lane)
    float4* __restrict__ gbuf,           // ring, taps 0..Q-1 already in flight
    const float (*__restrict__ s_hn)[TILE_W],
    const float* __restrict__ h0v,       // 4 preloaded h0 values
    float* __restrict__ out_row,
    int X0, int w, int l)
{
    const int x0 = X0 + 4 * l + D;

    float a0 = 0.f, a1 = 0.f, a2 = 0.f, a3 = 0.f;
    float win[16];

    #pragma unroll
    for (int t = 0; t < K2; ++t) {
        const int i = t / K;
        const int j = t - i * K;

        if (j == 0) {
            // refresh hn window for tap-row i (4 conflict-free LDS.128)
            const int r = w + 6 - i;
            const float4 wa = *reinterpret_cast<const float4*>(&s_hn[r][4 * l]);
            const float4 wb = *reinterpret_cast<const float4*>(&s_hn[r][4 * l + 4]);
            const float4 wc = *reinterpret_cast<const float4*>(&s_hn[r][4 * l + 8]);
            const float4 wd = *reinterpret_cast<const float4*>(&s_hn[r][4 * l + 12]);
            win[0] = wa.x;  win[1] = wa.y;  win[2]  = wa.z;  win[3]  = wa.w;
            win[4] = wb.x;  win[5] = wb.y;  win[6]  = wb.z;  win[7]  = wb.w;
            win[8] = wc.x;  win[9] = wc.y;  win[10] = wc.z;  win[11] = wc.w;
            win[12] = wd.x; win[13] = wd.y; win[14] = wd.z;  win[15] = wd.w;
        }

        const float4 g = gbuf[t % Q];
        if (t + Q < K2)
            gbuf[t % Q] = __ldcs(reinterpret_cast<const float4*>(
                                     p0 + (size_t)(t + Q) * PLANE));

        if (i == 3 && j == 3) {
            a0 = fmaf(g.x, h0v[0], a0);
            a1 = fmaf(g.y, h0v[1], a1);
            a2 = fmaf(g.z, h0v[2], a2);
            a3 = fmaf(g.w, h0v[3], a3);
        } else {
            a0 = fmaf(g.x, win[D + 0 + 6 - j], a0);
            a1 = fmaf(g.y, win[D + 1 + 6 - j], a1);
            a2 = fmaf(g.z, win[D + 2 + 6 - j], a2);
            a3 = fmaf(g.w, win[D + 3 + 6 - j], a3);
        }
    }

    if (x0 + 0 < W) __stcs(out_row + x0 + 0, a0);
    if (x0 + 1 < W) __stcs(out_row + x0 + 1, a1);
    if (x0 + 2 < W) __stcs(out_row + x0 + 2, a2);
    if (x0 + 3 < W) __stcs(out_row + x0 + 3, a3);
}

__global__ __launch_bounds__(NT, 5) void cspn_kernel(
    const float* __restrict__ gw,
    const float* __restrict__ hn,
    const float* __restrict__ h0,
    float* __restrict__ out)
{
    __shared__ __align__(16) float s_hn[TILE_H][TILE_W];

    // batch-interleaved scheduling: y = blockIdx.y is the batch (fast-ish dim),
    // blockIdx.z sweeps y-tiles (slow dim).
    const int b  = blockIdx.y;
    const int X0 = blockIdx.x * BX;
    const int Y0 = blockIdx.z * BY;
    const int tid = threadIdx.x;
    const int w = tid >> 5;
    const int l = tid & 31;

    // ---- compute gw base + alignment phase FIRST ----
    const int y = Y0 + w;
    const float* __restrict__ gw_b = gw + (size_t)b * K2 * PLANE;
    const float* rowp = gw_b + (size_t)(y + 3) * WP + 3 + X0;
    const int d = (int)((16u - ((uint32_t)(uintptr_t)rowp & 15u)) >> 2) & 3;  // 1 or 3
    const float* p0 = rowp + 4 * l + d;  // 16B-aligned

    // ---- hoisted ring prefetch: Q DRAM loads in flight before anything else ----
    float4 gbuf[Q];
    #pragma unroll
    for (int q = 0; q < Q; ++q)
        gbuf[q] = __ldcs(reinterpret_cast<const float4*>(p0 + (size_t)q * PLANE));

    // ---- stage hn halo tile (latency overlaps the ring fill) ----
    const float* __restrict__ hn_b = hn + (size_t)b * H * W;
    #pragma unroll
    for (int idx = tid; idx < TILE_H * TILE_W; idx += NT) {
        const int r  = idx / TILE_W;
        const int c  = idx - r * TILE_W;
        const int gy = Y0 - 3 + r;
        const int gx = X0 - 3 + c;
        float v = 0.0f;
        if ((unsigned)gy < (unsigned)H && (unsigned)gx < (unsigned)W)
            v = __ldg(hn_b + (size_t)gy * W + gx);
        s_hn[r][c] = v;
    }

    const float* h0_row = h0 + ((size_t)b * H + y) * W;
    float* out_row = out + ((size_t)b * H + y) * W;
    const int x0 = X0 + 4 * l + d;

    float h0v[4];
    #pragma unroll
    for (int m = 0; m < 4; ++m)
        h0v[m] = (x0 + m < W) ? __ldg(h0_row + x0 + m) : 0.0f;

    __syncthreads();

    if (d == 3)
        row_compute<3>(p0, gbuf, s_hn, h0v, out_row, X0, w, l);
    else
        row_compute<1>(p0, gbuf, s_hn, h0v, out_row, X0, w, l);

    // ---- left-edge outputs x in [0, d), leftmost blocks only ----
    if (X0 == 0 && l < d) {
        const int xe = l;
        const float h0e = __ldg(h0_row + xe);
        float acc = 0.0f;
        #pragma unroll
        for (int i = 0; i < K; ++i) {
            #pragma unroll
            for (int j = 0; j < K; ++j) {
                const float g = __ldcs(gw_b + (size_t)(i * K + j) * PLANE
                                       + (size_t)(y + 3) * WP + (xe + 3));
                const float v = (i == 3 && j == 3) ? h0e : s_hn[w + 6 - i][xe + 6 - j];
                acc = fmaf(g, v, acc);
            }
        }
        __stcs(out_row + xe, acc);
    }
}

extern "C" void kernel_launch(void* const* d_in, const int* in_sizes, int n_in,
                              void* d_out, int out_size)
{
    const float* gw = (const float*)d_in[0];
    const float* hn = (const float*)d_in[1];
    const float* h0 = (const float*)d_in[2];
    float* out = (float*)d_out;

    dim3 block(NT, 1, 1);
    dim3 grid(W / BX, B, H / BY);   // batch before y-tiles: wave spans all batches
    cspn_kernel<<<grid, block>>>(gw, hn, h0, out);
}

// round 15
// speedup vs baseline: 1.0312x; 1.0312x over previous
#include <cuda_runtime.h>
#include <cstddef>
#include <cstdint>

// CSPN_6468220748336 — FINAL (best measured 65.57us, ~98% of traffic-floor
// roofline; traffic = compulsory ~445MB exactly, DRAM ~81% avg).
// Config: vectorized ownership-shift, BY=4 tile (tail optimum), Q=8 register
// ring prefetch hoisted ahead of halo staging, batch-slow block order
// (page/sector locality — batch-interleave measured worse), 5 CTAs/SM.
// out[b,y,x] = sum_{i,j} gw[b, i*7+j, y+3, x+3] * src[b, y+3-i, x+3-j]
//   src = h0 at (i,j)=(3,3), else hn; zero-padded outside [0,512)^2.

namespace {
constexpr int K  = 7;
constexpr int K2 = 49;
constexpr int B  = 8;
constexpr int H  = 512;
constexpr int W  = 512;
constexpr int WP = 518;
constexpr int PLANE = WP * WP;

constexpr int BX = 128;                // output cols per block
constexpr int BY = 4;                  // output rows per block (1 warp/row)
constexpr int NT = 128;                // 4 warps

constexpr int Q  = 8;                  // prefetch lookahead (taps), ring size

constexpr int TILE_W = 140;            // hn halo cols [X0-3, X0+137)
constexpr int TILE_H = BY + K - 1;     // 10 halo rows [Y0-3, Y0+7)
}

template <int D>
__device__ __forceinline__ void row_compute(
    const float* __restrict__ p0,        // aligned float4 base, tap 0 (this lane)
    float4* __restrict__ gbuf,           // ring, taps 0..Q-1 already in flight
    const float (*__restrict__ s_hn)[TILE_W],
    const float* __restrict__ h0v,       // 4 preloaded h0 values
    float* __restrict__ out_row,
    int X0, int w, int l)
{
    const int x0 = X0 + 4 * l + D;

    float a0 = 0.f, a1 = 0.f, a2 = 0.f, a3 = 0.f;
    float win[16];

    #pragma unroll
    for (int t = 0; t < K2; ++t) {
        const int i = t / K;
        const int j = t - i * K;

        if (j == 0) {
            // refresh hn window for tap-row i (4 conflict-free LDS.128)
            const int r = w + 6 - i;
            const float4 wa = *reinterpret_cast<const float4*>(&s_hn[r][4 * l]);
            const float4 wb = *reinterpret_cast<const float4*>(&s_hn[r][4 * l + 4]);
            const float4 wc = *reinterpret_cast<const float4*>(&s_hn[r][4 * l + 8]);
            const float4 wd = *reinterpret_cast<const float4*>(&s_hn[r][4 * l + 12]);
            win[0] = wa.x;  win[1] = wa.y;  win[2]  = wa.z;  win[3]  = wa.w;
            win[4] = wb.x;  win[5] = wb.y;  win[6]  = wb.z;  win[7]  = wb.w;
            win[8] = wc.x;  win[9] = wc.y;  win[10] = wc.z;  win[11] = wc.w;
            win[12] = wd.x; win[13] = wd.y; win[14] = wd.z;  win[15] = wd.w;
        }

        const float4 g = gbuf[t % Q];
        if (t + Q < K2)
            gbuf[t % Q] = __ldcs(reinterpret_cast<const float4*>(
                                     p0 + (size_t)(t + Q) * PLANE));

        if (i == 3 && j == 3) {
            a0 = fmaf(g.x, h0v[0], a0);
            a1 = fmaf(g.y, h0v[1], a1);
            a2 = fmaf(g.z, h0v[2], a2);
            a3 = fmaf(g.w, h0v[3], a3);
        } else {
            a0 = fmaf(g.x, win[D + 0 + 6 - j], a0);
            a1 = fmaf(g.y, win[D + 1 + 6 - j], a1);
            a2 = fmaf(g.z, win[D + 2 + 6 - j], a2);
            a3 = fmaf(g.w, win[D + 3 + 6 - j], a3);
        }
    }

    if (x0 + 0 < W) __stcs(out_row + x0 + 0, a0);
    if (x0 + 1 < W) __stcs(out_row + x0 + 1, a1);
    if (x0 + 2 < W) __stcs(out_row + x0 + 2, a2);
    if (x0 + 3 < W) __stcs(out_row + x0 + 3, a3);
}

__global__ __launch_bounds__(NT, 5) void cspn_kernel(
    const float* __restrict__ gw,
    const float* __restrict__ hn,
    const float* __restrict__ h0,
    float* __restrict__ out)
{
    __shared__ __align__(16) float s_hn[TILE_H][TILE_W];

    const int b  = blockIdx.z;
    const int X0 = blockIdx.x * BX;
    const int Y0 = blockIdx.y * BY;
    const int tid = threadIdx.x;
    const int w = tid >> 5;
    const int l = tid & 31;

    // ---- compute gw base + alignment phase FIRST ----
    const int y = Y0 + w;
    const float* __restrict__ gw_b = gw + (size_t)b * K2 * PLANE;
    const float* rowp = gw_b + (size_t)(y + 3) * WP + 3 + X0;
    const int d = (int)((16u - ((uint32_t)(uintptr_t)rowp & 15u)) >> 2) & 3;  // 1 or 3
    const float* p0 = rowp + 4 * l + d;  // 16B-aligned

    // ---- hoisted ring prefetch: Q DRAM loads in flight before anything else ----
    float4 gbuf[Q];
    #pragma unroll
    for (int q = 0; q < Q; ++q)
        gbuf[q] = __ldcs(reinterpret_cast<const float4*>(p0 + (size_t)q * PLANE));

    // ---- stage hn halo tile (latency overlaps the ring fill) ----
    const float* __restrict__ hn_b = hn + (size_t)b * H * W;
    #pragma unroll
    for (int idx = tid; idx < TILE_H * TILE_W; idx += NT) {
        const int r  = idx / TILE_W;
        const int c  = idx - r * TILE_W;
        const int gy = Y0 - 3 + r;
        const int gx = X0 - 3 + c;
        float v = 0.0f;
        if ((unsigned)gy < (unsigned)H && (unsigned)gx < (unsigned)W)
            v = __ldg(hn_b + (size_t)gy * W + gx);
        s_hn[r][c] = v;
    }

    const float* h0_row = h0 + ((size_t)b * H + y) * W;
    float* out_row = out + ((size_t)b * H + y) * W;
    const int x0 = X0 + 4 * l + d;

    float h0v[4];
    #pragma unroll
    for (int m = 0; m < 4; ++m)
        h0v[m] = (x0 + m < W) ? __ldg(h0_row + x0 + m) : 0.0f;

    __syncthreads();

    if (d == 3)
        row_compute<3>(p0, gbuf, s_hn, h0v, out_row, X0, w, l);
    else
        row_compute<1>(p0, gbuf, s_hn, h0v, out_row, X0, w, l);

    // ---- left-edge outputs x in [0, d), leftmost blocks only ----
    if (X0 == 0 && l < d) {
        const int xe = l;
        const float h0e = __ldg(h0_row + xe);
        float acc = 0.0f;
        #pragma unroll
        for (int i = 0; i < K; ++i) {
            #pragma unroll
            for (int j = 0; j < K; ++j) {
                const float g = __ldcs(gw_b + (size_t)(i * K + j) * PLANE
                                       + (size_t)(y + 3) * WP + (xe + 3));
                const float v = (i == 3 && j == 3) ? h0e : s_hn[w + 6 - i][xe + 6 - j];
                acc = fmaf(g, v, acc);
            }
        }
        __stcs(out_row + xe, acc);
    }
}

extern "C" void kernel_launch(void* const* d_in, const int* in_sizes, int n_in,
                              void* d_out, int out_size)
{
    const float* gw = (const float*)d_in[0];
    const float* hn = (const float*)d_in[1];
    const float* h0 = (const float*)d_in[2];
    float* out = (float*)d_out;

    dim3 block(NT, 1, 1);
    dim3 grid(W / BX, H / BY, B);
    cspn_kernel<<<grid, block>>>(gw, hn, h0, out);
}